// round 2
// baseline (speedup 1.0000x reference)
#include <cuda_runtime.h>
#include <math.h>

#define Bb  2
#define Ss  2048
#define Hh  1024
#define NHh 16
#define HDd 64

// Scratch (allocation-free rule: __device__ globals)
__device__ float g_Q[(size_t)Bb * NHh * Ss * HDd];
__device__ float g_K[(size_t)Bb * NHh * Ss * HDd];
__device__ float g_V[(size_t)Bb * NHh * Ss * HDd];
__device__ float g_ctx[(size_t)Bb * Ss * Hh];
__device__ float g_gain[(size_t)Bb * Ss * NHh];

// ---------------------------------------------------------------------------
// K1: per-(b,s) gating. gain[b,s,h] = (1+sig(pros@pg_w+pg_b)[h])
//                                   * (1+0.5*sig(hs@mg_w+mg_b)) / sqrt(HD)
// ---------------------------------------------------------------------------
__global__ __launch_bounds__(256) void gate_kernel(
    const float* __restrict__ hs, const float* __restrict__ pros,
    const float* __restrict__ pg_w, const float* __restrict__ pg_b,
    const float* __restrict__ mg_w, const float* __restrict__ mg_b)
{
    int bs = blockIdx.x;                 // 0..B*S-1
    const float* x = hs + (size_t)bs * Hh;
    int tid = threadIdx.x;

    float part = 0.f;
    for (int i = tid; i < Hh; i += 256) part += x[i] * mg_w[i];
    __shared__ float red[256];
    red[tid] = part; __syncthreads();
    for (int s = 128; s > 0; s >>= 1) {
        if (tid < s) red[tid] += red[tid + s];
        __syncthreads();
    }
    float mem = 1.0f + 0.5f / (1.0f + __expf(-(red[0] + mg_b[0])));

    if (tid < NHh) {
        const float* p = pros + (size_t)bs * 4;
        float a = p[0] * pg_w[0 * NHh + tid] + p[1] * pg_w[1 * NHh + tid]
                + p[2] * pg_w[2 * NHh + tid] + p[3] * pg_w[3 * NHh + tid]
                + pg_b[tid];
        float pg = 1.0f + 1.0f / (1.0f + __expf(-a));
        g_gain[(size_t)bs * NHh + tid] = pg * mem * 0.125f;  // includes 1/sqrt(64)
    }
}

// ---------------------------------------------------------------------------
// K2: QKV projection. X[4096,1024] @ W[1024,1024] + b.
// 128x128x8 fp32 tiles, 8x8 per thread. blockIdx.z selects Q/K/V.
// Epilogue: head-major [b,h,s,d]; z==0 applies the folded gain.
// ---------------------------------------------------------------------------
__global__ __launch_bounds__(256) void qkv_gemm(
    const float* __restrict__ X,
    const float* __restrict__ Wq, const float* __restrict__ bq,
    const float* __restrict__ Wk, const float* __restrict__ bk,
    const float* __restrict__ Wv, const float* __restrict__ bv)
{
    const int z = blockIdx.z;
    const float* W    = (z == 0) ? Wq : (z == 1) ? Wk : Wv;
    const float* bias = (z == 0) ? bq : (z == 1) ? bk : bv;
    float* out        = (z == 0) ? g_Q : (z == 1) ? g_K : g_V;

    const int n0 = blockIdx.x * 128;
    const int m0 = blockIdx.y * 128;

    __shared__ float As[8][128];
    __shared__ float Bs[8][128];

    int tid = threadIdx.x;
    int ry = tid >> 4, cx = tid & 15;

    float acc[8][8];
#pragma unroll
    for (int i = 0; i < 8; i++)
#pragma unroll
        for (int j = 0; j < 8; j++) acc[i][j] = 0.f;

    for (int kt = 0; kt < 1024; kt += 8) {
        {   // A tile 128x8, transposed into As[k][m]
            int row = tid >> 1, kq = tid & 1;
            float4 v = *(const float4*)(X + (size_t)(m0 + row) * 1024 + kt + kq * 4);
            As[kq * 4 + 0][row] = v.x; As[kq * 4 + 1][row] = v.y;
            As[kq * 4 + 2][row] = v.z; As[kq * 4 + 3][row] = v.w;
        }
        {   // B tile 8x128
            int k = tid >> 5, nq = tid & 31;
            float4 v = *(const float4*)(W + (size_t)(kt + k) * 1024 + n0 + nq * 4);
            *(float4*)&Bs[k][nq * 4] = v;
        }
        __syncthreads();
#pragma unroll
        for (int k = 0; k < 8; k++) {
            float a[8], b[8];
            *(float4*)&a[0] = *(float4*)&As[k][ry * 8];
            *(float4*)&a[4] = *(float4*)&As[k][ry * 8 + 4];
            *(float4*)&b[0] = *(float4*)&Bs[k][cx * 8];
            *(float4*)&b[4] = *(float4*)&Bs[k][cx * 8 + 4];
#pragma unroll
            for (int i = 0; i < 8; i++)
#pragma unroll
                for (int j = 0; j < 8; j++) acc[i][j] += a[i] * b[j];
        }
        __syncthreads();
    }

#pragma unroll
    for (int i = 0; i < 8; i++) {
        int m = m0 + ry * 8 + i;
        int bidx = m / Ss, srow = m % Ss;
#pragma unroll
        for (int j = 0; j < 8; j++) {
            int col = n0 + cx * 8 + j;
            float v = acc[i][j] + bias[col];
            int h = col >> 6, d = col & 63;
            if (z == 0) v *= g_gain[(size_t)m * NHh + h];
            out[(((size_t)(bidx * NHh + h)) * Ss + srow) * HDd + d] = v;
        }
    }
}

// ---------------------------------------------------------------------------
// K3: raw scores, lower-triangle tiles only. 128x128 outputs per block,
// K-dim = 64 processed in two d-chunks of 32. Writes straight into d_out.
// ---------------------------------------------------------------------------
__global__ __launch_bounds__(256) void scores_kernel(float* __restrict__ attn)
{
    int kt = blockIdx.x, qt = blockIdx.y, bh = blockIdx.z;
    if (kt > qt) return;

    const float* Qg = g_Q + (size_t)bh * Ss * HDd;
    const float* Kg = g_K + (size_t)bh * Ss * HDd;

    __shared__ float Qs[32][128];
    __shared__ float Ks[32][128];

    int tid = threadIdx.x;
    int ry = tid >> 4, cx = tid & 15;
    int q0 = qt * 128, k0 = kt * 128;

    float acc[8][8];
#pragma unroll
    for (int i = 0; i < 8; i++)
#pragma unroll
        for (int j = 0; j < 8; j++) acc[i][j] = 0.f;

    for (int dc = 0; dc < 64; dc += 32) {
        for (int f = tid; f < 1024; f += 256) {
            int row = f >> 3, q4 = f & 7;
            float4 v = *(const float4*)(Qg + (size_t)(q0 + row) * HDd + dc + q4 * 4);
            Qs[q4 * 4 + 0][row] = v.x; Qs[q4 * 4 + 1][row] = v.y;
            Qs[q4 * 4 + 2][row] = v.z; Qs[q4 * 4 + 3][row] = v.w;
            float4 w = *(const float4*)(Kg + (size_t)(k0 + row) * HDd + dc + q4 * 4);
            Ks[q4 * 4 + 0][row] = w.x; Ks[q4 * 4 + 1][row] = w.y;
            Ks[q4 * 4 + 2][row] = w.z; Ks[q4 * 4 + 3][row] = w.w;
        }
        __syncthreads();
#pragma unroll 8
        for (int k = 0; k < 32; k++) {
            float a[8], b[8];
            *(float4*)&a[0] = *(float4*)&Qs[k][ry * 8];
            *(float4*)&a[4] = *(float4*)&Qs[k][ry * 8 + 4];
            *(float4*)&b[0] = *(float4*)&Ks[k][cx * 8];
            *(float4*)&b[4] = *(float4*)&Ks[k][cx * 8 + 4];
#pragma unroll
            for (int i = 0; i < 8; i++)
#pragma unroll
                for (int j = 0; j < 8; j++) acc[i][j] += a[i] * b[j];
        }
        __syncthreads();
    }

    float* abase = attn + (size_t)bh * Ss * Ss;
#pragma unroll
    for (int i = 0; i < 8; i++) {
        int gi = q0 + ry * 8 + i;
#pragma unroll
        for (int j = 0; j < 8; j++) {
            int gj = k0 + cx * 8 + j;
            abase[(size_t)gi * Ss + gj] = (gj <= gi) ? acc[i][j] : -INFINITY;
        }
    }
}

// ---------------------------------------------------------------------------
// K4: row softmax in-place + zero-fill above the diagonal.
// One block per row; row held in registers (<= 8 elems/thread).
// ---------------------------------------------------------------------------
__global__ __launch_bounds__(256) void softmax_kernel(float* __restrict__ attn)
{
    int i = blockIdx.x, h = blockIdx.y, b = blockIdx.z;
    float* row = attn + ((size_t)(b * NHh + h) * Ss + i) * Ss;
    int n = i + 1;
    int tid = threadIdx.x;

    float vals[8];
    int cnt = 0;
    float mx = -INFINITY;
    for (int j = tid; j < n; j += 256) {
        float s = row[j];
        vals[cnt++] = s;
        mx = fmaxf(mx, s);
    }

    __shared__ float red[256];
    red[tid] = mx; __syncthreads();
    for (int s = 128; s > 0; s >>= 1) {
        if (tid < s) red[tid] = fmaxf(red[tid], red[tid + s]);
        __syncthreads();
    }
    mx = red[0];
    __syncthreads();

    float sum = 0.f;
    for (int c = 0; c < cnt; c++) {
        vals[c] = __expf(vals[c] - mx);
        sum += vals[c];
    }
    red[tid] = sum; __syncthreads();
    for (int s = 128; s > 0; s >>= 1) {
        if (tid < s) red[tid] += red[tid + s];
        __syncthreads();
    }
    float inv = 1.0f / red[0];

    cnt = 0;
    for (int j = tid; j < n; j += 256) row[j] = vals[cnt++] * inv;
    for (int j = n + tid; j < Ss; j += 256) row[j] = 0.f;
}

// ---------------------------------------------------------------------------
// K5: context = attn @ V (causal: skip k-tiles beyond the diagonal).
// 128x64 outputs per block, 8x4 per thread, BK=64.
// ---------------------------------------------------------------------------
__global__ __launch_bounds__(256) void pv_kernel(const float* __restrict__ attn)
{
    int qt = blockIdx.x, bh = blockIdx.y;
    int b = bh / NHh, h = bh % NHh;
    const float* Vg = g_V + (size_t)bh * Ss * HDd;
    const float* abase = attn + (size_t)bh * Ss * Ss;

    __shared__ float As[64][128];  // [k][m]
    __shared__ float Bs[64][64];   // [k][d]

    int tid = threadIdx.x;
    int ry = tid >> 4, cx = tid & 15;
    int q0 = qt * 128;

    float acc[8][4];
#pragma unroll
    for (int i = 0; i < 8; i++)
#pragma unroll
        for (int j = 0; j < 4; j++) acc[i][j] = 0.f;

    int kend = (qt + 1) * 128;
    for (int k0 = 0; k0 < kend; k0 += 64) {
        for (int f = tid; f < 2048; f += 256) {   // 128 rows x 16 float4
            int row = f >> 4, q4 = f & 15;
            float4 v = *(const float4*)(abase + (size_t)(q0 + row) * Ss + k0 + q4 * 4);
            As[q4 * 4 + 0][row] = v.x; As[q4 * 4 + 1][row] = v.y;
            As[q4 * 4 + 2][row] = v.z; As[q4 * 4 + 3][row] = v.w;
        }
        for (int f = tid; f < 1024; f += 256) {   // 64 rows x 16 float4
            int kk = f >> 4, q4 = f & 15;
            *(float4*)&Bs[kk][q4 * 4] =
                *(const float4*)(Vg + (size_t)(k0 + kk) * HDd + q4 * 4);
        }
        __syncthreads();
#pragma unroll 8
        for (int k = 0; k < 64; k++) {
            float a[8], bvec[4];
            *(float4*)&a[0] = *(float4*)&As[k][ry * 8];
            *(float4*)&a[4] = *(float4*)&As[k][ry * 8 + 4];
            *(float4*)&bvec[0] = *(float4*)&Bs[k][cx * 4];
#pragma unroll
            for (int i = 0; i < 8; i++)
#pragma unroll
                for (int j = 0; j < 4; j++) acc[i][j] += a[i] * bvec[j];
        }
        __syncthreads();
    }

#pragma unroll
    for (int i = 0; i < 8; i++) {
        int srow = q0 + ry * 8 + i;
#pragma unroll
        for (int j = 0; j < 4; j++) {
            int d = cx * 4 + j;
            g_ctx[((size_t)b * Ss + srow) * Hh + h * 64 + d] = acc[i][j];
        }
    }
}

// ---------------------------------------------------------------------------
// K6: output projection. g_ctx[4096,1024] @ o_w + o_b -> d_out[0 : B*S*H]
// ---------------------------------------------------------------------------
__global__ __launch_bounds__(256) void out_gemm(
    const float* __restrict__ W, const float* __restrict__ bias,
    float* __restrict__ out)
{
    const float* X = g_ctx;
    const int n0 = blockIdx.x * 128;
    const int m0 = blockIdx.y * 128;

    __shared__ float As[8][128];
    __shared__ float Bs[8][128];

    int tid = threadIdx.x;
    int ry = tid >> 4, cx = tid & 15;

    float acc[8][8];
#pragma unroll
    for (int i = 0; i < 8; i++)
#pragma unroll
        for (int j = 0; j < 8; j++) acc[i][j] = 0.f;

    for (int kt = 0; kt < 1024; kt += 8) {
        {
            int row = tid >> 1, kq = tid & 1;
            float4 v = *(const float4*)(X + (size_t)(m0 + row) * 1024 + kt + kq * 4);
            As[kq * 4 + 0][row] = v.x; As[kq * 4 + 1][row] = v.y;
            As[kq * 4 + 2][row] = v.z; As[kq * 4 + 3][row] = v.w;
        }
        {
            int k = tid >> 5, nq = tid & 31;
            float4 v = *(const float4*)(W + (size_t)(kt + k) * 1024 + n0 + nq * 4);
            *(float4*)&Bs[k][nq * 4] = v;
        }
        __syncthreads();
#pragma unroll
        for (int k = 0; k < 8; k++) {
            float a[8], b[8];
            *(float4*)&a[0] = *(float4*)&As[k][ry * 8];
            *(float4*)&a[4] = *(float4*)&As[k][ry * 8 + 4];
            *(float4*)&b[0] = *(float4*)&Bs[k][cx * 8];
            *(float4*)&b[4] = *(float4*)&Bs[k][cx * 8 + 4];
#pragma unroll
            for (int i = 0; i < 8; i++)
#pragma unroll
                for (int j = 0; j < 8; j++) acc[i][j] += a[i] * b[j];
        }
        __syncthreads();
    }

#pragma unroll
    for (int i = 0; i < 8; i++) {
        int m = m0 + ry * 8 + i;
#pragma unroll
        for (int j = 0; j < 8; j++) {
            int col = n0 + cx * 8 + j;
            out[(size_t)m * Hh + col] = acc[i][j] + bias[col];
        }
    }
}

// ---------------------------------------------------------------------------
extern "C" void kernel_launch(void* const* d_in, const int* in_sizes, int n_in,
                              void* d_out, int out_size)
{
    const float* hs   = (const float*)d_in[0];
    const float* pros = (const float*)d_in[1];
    const float* q_w  = (const float*)d_in[2];
    const float* q_b  = (const float*)d_in[3];
    const float* k_w  = (const float*)d_in[4];
    const float* k_b  = (const float*)d_in[5];
    const float* v_w  = (const float*)d_in[6];
    const float* v_b  = (const float*)d_in[7];
    const float* o_w  = (const float*)d_in[8];
    const float* o_b  = (const float*)d_in[9];
    const float* pg_w = (const float*)d_in[10];
    const float* pg_b = (const float*)d_in[11];
    const float* mg_w = (const float*)d_in[12];
    const float* mg_b = (const float*)d_in[13];

    float* out  = (float*)d_out;
    float* attn = out + (size_t)Bb * Ss * Hh;

    gate_kernel<<<Bb * Ss, 256>>>(hs, pros, pg_w, pg_b, mg_w, mg_b);
    qkv_gemm<<<dim3(8, 32, 3), 256>>>(hs, q_w, q_b, k_w, k_b, v_w, v_b);
    scores_kernel<<<dim3(16, 16, 32), 256>>>(attn);
    softmax_kernel<<<dim3(Ss, NHh, Bb), 256>>>(attn);
    pv_kernel<<<dim3(16, 32), 256>>>(attn);
    out_gemm<<<dim3(8, 32), 256>>>(o_w, o_b, out);
}